// round 6
// baseline (speedup 1.0000x reference)
#include <cuda_runtime.h>
#include <math.h>

#define NN   50000
#define EE   800000
#define DIN  96
#define DD   128
#define BB   512
#define KCAT 384
#define GOUT 512

// ---------------- scratch (static device globals; no allocs) ----------------
__device__ __align__(16) float g_hA[NN*DD];          // 25.6 MB
__device__ __align__(16) float g_hB[NN*DD];          // 25.6 MB
__device__ __align__(16) float g_WinT[DIN*DD];       // W_in transposed [k][d]
__device__ __align__(16) float g_WcatT[KCAT*GOUT];   // [k][o]: 0..255 = W_ih^T, 256..383 = W_hh^T
__device__ __align__(16) int   g_deg[NN];
__device__ __align__(16) float g_degf[NN];
__device__ __align__(16) int   g_rowptr[NN+4];
__device__ __align__(16) int   g_cursor[NN];
__device__ __align__(16) int   g_col[EE];
__device__ __align__(16) int   g_part[128];
__device__ __align__(16) int   g_gptr[BB+4];
__device__ __align__(16) float g_e[NN];
__device__ __align__(16) float g_emax[BB];
__device__ __align__(16) float g_qh[BB*KCAT];        // per graph: [q(128) | r(128) | hh(128)]
__device__ __align__(16) float g_cc[BB*DD];
__device__ __align__(16) float g_gates[BB*GOUT];

// ---------------- helpers ----------------
__device__ __forceinline__ float sigm(float x) { return 1.f / (1.f + expf(-x)); }

// ---------------- init ----------------
__global__ void k_zero() {
    int i = blockIdx.x * blockDim.x + threadIdx.x;   // grid covers 196608 exactly
    if (i < NN)        g_deg[i] = 0;
    if (i < BB*KCAT)   g_qh[i]  = 0.f;
    if (i < BB*DD)     g_cc[i]  = 0.f;
}

__global__ void k_transpose(const float* __restrict__ W_in,
                            const float* __restrict__ W_ih,
                            const float* __restrict__ W_hh) {
    int i = blockIdx.x * blockDim.x + threadIdx.x;   // 196608 threads
    if (i < DIN*DD) {
        int k = i >> 7, d = i & (DD-1);
        g_WinT[i] = W_in[d*DIN + k];
    }
    int k = i >> 9, o = i & (GOUT-1);                // i < KCAT*GOUT = 196608
    g_WcatT[i] = (k < 256) ? W_ih[o*256 + k] : W_hh[o*128 + (k - 256)];
}

// ---------------- input layer: h = relu(x @ W_in^T + b_in) ----------------
__global__ __launch_bounds__(128) void k_ingemm(const float* __restrict__ x,
                                                const float* __restrict__ b_in) {
    __shared__ float xs[32*DIN];
    int node0 = blockIdx.x * 32;
    int t = threadIdx.x;
    for (int i = t; i < 32*DIN; i += 128) {
        int node = node0 + i / DIN;
        xs[i] = (node < NN) ? x[node0*DIN + i] : 0.f;
    }
    __syncthreads();
    int tx = t & 31, ty = t >> 5;
    float acc[8][4];
    float4 bv = *(const float4*)(b_in + tx*4);
    #pragma unroll
    for (int n = 0; n < 8; n++) { acc[n][0]=bv.x; acc[n][1]=bv.y; acc[n][2]=bv.z; acc[n][3]=bv.w; }
    #pragma unroll 4
    for (int k = 0; k < DIN; k++) {
        float4 w = *(const float4*)(g_WinT + k*DD + tx*4);
        #pragma unroll
        for (int n = 0; n < 8; n++) {
            float xv = xs[(ty*8+n)*DIN + k];
            acc[n][0] += w.x*xv; acc[n][1] += w.y*xv;
            acc[n][2] += w.z*xv; acc[n][3] += w.w*xv;
        }
    }
    #pragma unroll
    for (int n = 0; n < 8; n++) {
        int node = node0 + ty*8 + n;
        if (node < NN) {
            float4 o;
            o.x = fmaxf(acc[n][0], 0.f); o.y = fmaxf(acc[n][1], 0.f);
            o.z = fmaxf(acc[n][2], 0.f); o.w = fmaxf(acc[n][3], 0.f);
            *(float4*)(g_hA + node*DD + tx*4) = o;
        }
    }
}

// ---------------- CSR build (edge_index is int32: JAX default demotes int64) --
__global__ void k_hist(const int* __restrict__ ei) {
    int i = blockIdx.x * blockDim.x + threadIdx.x;
    if (i < EE) atomicAdd(&g_deg[ei[EE + i]], 1);
}

__global__ void k_scan1() {
    __shared__ int s[512];
    int t = threadIdx.x, i = blockIdx.x*512 + t;
    s[t] = (i < NN) ? g_deg[i] : 0;
    __syncthreads();
    for (int o = 256; o > 0; o >>= 1) { if (t < o) s[t] += s[t+o]; __syncthreads(); }
    if (t == 0) g_part[blockIdx.x] = s[0];
}

__global__ void k_scan2() {
    __shared__ int s[128];
    int t = threadIdx.x;
    int v = (t < 98) ? g_part[t] : 0;
    s[t] = v; __syncthreads();
    for (int off = 1; off < 128; off <<= 1) {
        int add = (t >= off) ? s[t-off] : 0;
        __syncthreads();
        s[t] += add;
        __syncthreads();
    }
    g_part[t] = s[t] - v;   // exclusive
}

__global__ void k_scan3() {
    __shared__ int s[512];
    int t = threadIdx.x, i = blockIdx.x*512 + t;
    int cnt = (i < NN) ? g_deg[i] : 0;
    s[t] = cnt; __syncthreads();
    for (int off = 1; off < 512; off <<= 1) {
        int add = (t >= off) ? s[t-off] : 0;
        __syncthreads();
        s[t] += add;
        __syncthreads();
    }
    int excl = s[t] - cnt + g_part[blockIdx.x];
    if (i < NN) {
        g_rowptr[i] = excl;
        g_cursor[i] = excl;
        g_degf[i]   = (float)(cnt > 1 ? cnt : 1);
        if (i == NN-1) g_rowptr[NN] = excl + cnt;
    }
}

__global__ void k_fill(const int* __restrict__ ei) {
    int i = blockIdx.x * blockDim.x + threadIdx.x;
    if (i < EE) {
        int dst = ei[EE + i];
        int p = atomicAdd(&g_cursor[dst], 1);
        g_col[p] = ei[i];
    }
}

// ---------------- graph ranges from sorted batch (int32) ----------------
__global__ void k_gptr(const int* __restrict__ batch) {
    int n = blockIdx.x * blockDim.x + threadIdx.x;
    if (n >= NN) return;
    int b = batch[n];
    if (n == 0) { for (int q = 0; q <= b; q++) g_gptr[q] = 0; }
    else {
        int bp = batch[n-1];
        for (int q = bp+1; q <= b; q++) g_gptr[q] = n;
    }
    if (n == NN-1) { for (int q = b+1; q <= BB; q++) g_gptr[q] = NN; }
}

// ---------------- one MPNN step: warp per node, float4 per lane ----------------
__global__ __launch_bounds__(128) void k_mpnn(int dir) {
    const float* __restrict__ hin  = dir ? g_hB : g_hA;
    float*       __restrict__ hout = dir ? g_hA : g_hB;
    int gid = blockIdx.x * blockDim.x + threadIdx.x;
    int v = gid >> 5, lane = gid & 31;
    if (v >= NN) return;
    int rs = g_rowptr[v], re = g_rowptr[v+1];
    float ax = 0.f, ay = 0.f, az = 0.f, aw = 0.f;
    int j = rs;
    for (; j + 3 < re; j += 4) {
        int s0 = g_col[j], s1 = g_col[j+1], s2 = g_col[j+2], s3 = g_col[j+3];
        float4 v0 = *(const float4*)(hin + s0*DD + lane*4);
        float4 v1 = *(const float4*)(hin + s1*DD + lane*4);
        float4 v2 = *(const float4*)(hin + s2*DD + lane*4);
        float4 v3 = *(const float4*)(hin + s3*DD + lane*4);
        ax += v0.x + v1.x + v2.x + v3.x;
        ay += v0.y + v1.y + v2.y + v3.y;
        az += v0.z + v1.z + v2.z + v3.z;
        aw += v0.w + v1.w + v2.w + v3.w;
    }
    for (; j < re; j++) {
        int s0 = g_col[j];
        float4 v0 = *(const float4*)(hin + s0*DD + lane*4);
        ax += v0.x; ay += v0.y; az += v0.z; aw += v0.w;
    }
    float inv = 1.f / g_degf[v];
    float4 sf = *(const float4*)(hin + v*DD + lane*4);
    float4 o;
    o.x = (sf.x + ax*inv) * 0.5f;
    o.y = (sf.y + ay*inv) * 0.5f;
    o.z = (sf.z + az*inv) * 0.5f;
    o.w = (sf.w + aw*inv) * 0.5f;
    *(float4*)(hout + v*DD + lane*4) = o;
}

// ---------------- LSTM gates GEMM: gates[512,512] = qh[512,384] @ WcatT -------
__global__ __launch_bounds__(128) void k_gates(const float* __restrict__ b_ih,
                                               const float* __restrict__ b_hh) {
    __shared__ float qs[16*KCAT];    // 24 KB
    int g0 = (blockIdx.x & 31) * 16;
    int o0 = (blockIdx.x >> 5) * 128;
    int t = threadIdx.x;
    for (int i = t; i < 16*KCAT; i += 128) qs[i] = g_qh[g0*KCAT + i];
    __syncthreads();
    int tx = t & 31, ty = t >> 5;
    int o = o0 + tx*4;
    float4 bi = *(const float4*)(b_ih + o);
    float4 bh = *(const float4*)(b_hh + o);
    float acc[4][4];
    #pragma unroll
    for (int n = 0; n < 4; n++) {
        acc[n][0] = bi.x + bh.x; acc[n][1] = bi.y + bh.y;
        acc[n][2] = bi.z + bh.z; acc[n][3] = bi.w + bh.w;
    }
    #pragma unroll 4
    for (int k = 0; k < KCAT; k++) {
        float4 w = *(const float4*)(g_WcatT + k*GOUT + o);
        #pragma unroll
        for (int n = 0; n < 4; n++) {
            float xv = qs[(ty*4+n)*KCAT + k];
            acc[n][0] += w.x*xv; acc[n][1] += w.y*xv;
            acc[n][2] += w.z*xv; acc[n][3] += w.w*xv;
        }
    }
    #pragma unroll
    for (int n = 0; n < 4; n++) {
        float4 ov; ov.x = acc[n][0]; ov.y = acc[n][1]; ov.z = acc[n][2]; ov.w = acc[n][3];
        *(float4*)(g_gates + (g0 + ty*4 + n)*GOUT + o) = ov;
    }
}

__global__ void k_lstm() {
    int idx = blockIdx.x * blockDim.x + threadIdx.x;
    if (idx >= BB*DD) return;
    int b = idx >> 7, d = idx & 127;
    const float* g = g_gates + b*GOUT;
    float c = sigm(g[128+d]) * g_cc[idx] + sigm(g[d]) * tanhf(g[256+d]);
    float h = sigm(g[384+d]) * tanhf(c);
    g_cc[idx] = c;
    g_qh[b*KCAT + 256 + d] = h;   // hh (LSTM state, next gates input)
    g_qh[b*KCAT + d]       = h;   // q part of q_star
}

// ---------------- attention pass 1: e[n] = h[n].q[batch[n]], per-graph max ----
__global__ __launch_bounds__(256) void k_attn_e() {
    __shared__ __align__(16) float qsm[DD];
    __shared__ float wmax[8];
    int b = blockIdx.x, t = threadIdx.x;
    if (t < DD) qsm[t] = g_qh[b*KCAT + 256 + t];
    __syncthreads();
    int lane = t & 31, w = t >> 5;
    int ns = g_gptr[b], ne = g_gptr[b+1];
    float4 qv = *(const float4*)(qsm + lane*4);
    float m = -INFINITY;
    for (int n = ns + w; n < ne; n += 8) {
        float4 hv = *(const float4*)(g_hA + n*DD + lane*4);
        float p = hv.x*qv.x + hv.y*qv.y + hv.z*qv.z + hv.w*qv.w;
        for (int off = 16; off > 0; off >>= 1) p += __shfl_xor_sync(0xffffffffu, p, off);
        if (lane == 0) g_e[n] = p;
        m = fmaxf(m, p);
    }
    if (lane == 0) wmax[w] = m;
    __syncthreads();
    if (t == 0) {
        float mm = wmax[0];
        #pragma unroll
        for (int i = 1; i < 8; i++) mm = fmaxf(mm, wmax[i]);
        g_emax[b] = mm;
    }
}

// ---------------- attention pass 2: r[b] = sum exp(e-emax)*h / (sum exp) ------
__global__ __launch_bounds__(128) void k_attn_r() {
    int b = blockIdx.x, t = threadIdx.x;
    int ns = g_gptr[b], ne = g_gptr[b+1];
    float em = g_emax[b];
    float acc = 0.f, asum = 0.f;
    for (int n = ns; n < ne; n++) {
        float wv = expf(g_e[n] - em);
        asum += wv;
        acc  += wv * g_hA[n*DD + t];
    }
    g_qh[b*KCAT + DD + t] = acc / (asum + 1e-16f);   // r part of q_star
}

// ---------------- final prediction ----------------
__global__ void k_pred(const float* __restrict__ Wp, const float* __restrict__ bp,
                       float* __restrict__ out) {
    int b = blockIdx.x * blockDim.x + threadIdx.x;
    if (b >= BB) return;
    float s = bp[0];
    const float* q = g_qh + b*KCAT;
    #pragma unroll 8
    for (int k = 0; k < 256; k++) s += q[k] * Wp[k];
    out[b] = s;
}

// ---------------- launch ----------------
extern "C" void kernel_launch(void* const* d_in, const int* in_sizes, int n_in,
                              void* d_out, int out_size) {
    // Map inputs by element count (robust to metadata ordering).
    // Counts: x=4800000, edge_index=1600000, batch=50000, W_in=12288, b_in=128,
    //         W_ih=131072, W_hh=65536, b_ih=512, b_hh=512 (order: ih first),
    //         W_pred=256, b_pred=1.
    const float *x=0, *W_in=0, *b_in=0, *W_ih=0, *W_hh=0, *b_ih=0, *b_hh=0, *W_pred=0, *b_pred=0;
    const int *ei=0, *batch=0;
    for (int i = 0; i < n_in; i++) {
        int s = in_sizes[i];
        const void* p = d_in[i];
        switch (s) {
            case 4800000: x      = (const float*)p; break;
            case 1600000: ei     = (const int*)p;   break;
            case 50000:   batch  = (const int*)p;   break;
            case 12288:   W_in   = (const float*)p; break;
            case 128:     b_in   = (const float*)p; break;
            case 131072:  W_ih   = (const float*)p; break;
            case 65536:   W_hh   = (const float*)p; break;
            case 512:     if (!b_ih) b_ih = (const float*)p; else b_hh = (const float*)p; break;
            case 256:     W_pred = (const float*)p; break;
            case 1:       b_pred = (const float*)p; break;
            default: break;
        }
    }
    float* out = (float*)d_out;
    (void)out_size;

    k_zero<<<768, 256>>>();                       // 196608 threads
    k_transpose<<<768, 256>>>(W_in, W_ih, W_hh);
    k_ingemm<<<(NN + 31)/32, 128>>>(x, b_in);     // 1563 blocks
    k_hist<<<(EE + 255)/256, 256>>>(ei);
    k_scan1<<<98, 512>>>();
    k_scan2<<<1, 128>>>();
    k_scan3<<<98, 512>>>();
    k_fill<<<(EE + 255)/256, 256>>>(ei);
    k_gptr<<<(NN + 255)/256, 256>>>(batch);

    k_mpnn<<<(NN*32 + 127)/128, 128>>>(0);        // hA -> hB
    k_mpnn<<<(NN*32 + 127)/128, 128>>>(1);        // hB -> hA
    k_mpnn<<<(NN*32 + 127)/128, 128>>>(0);        // hA -> hB
    k_mpnn<<<(NN*32 + 127)/128, 128>>>(1);        // hB -> hA  (final h in g_hA)

    for (int s = 0; s < 3; s++) {
        k_gates<<<128, 128>>>(b_ih, b_hh);
        k_lstm<<<(BB*DD + 255)/256, 256>>>();
        k_attn_e<<<BB, 256>>>();
        k_attn_r<<<BB, 128>>>();
    }
    k_pred<<<(BB + 127)/128, 128>>>(W_pred, b_pred, out);
}

// round 12
// speedup vs baseline: 1.0189x; 1.0189x over previous
#include <cuda_runtime.h>
#include <math.h>

#define NN   50000
#define EE   800000
#define DIN  96
#define DD   128
#define BB   512
#define KCAT 384
#define GOUT 512

// ---------------- scratch (static device globals; no allocs) ----------------
__device__ __align__(16) float g_hA[NN*DD];          // 25.6 MB
__device__ __align__(16) float g_hB[NN*DD];          // 25.6 MB
__device__ __align__(16) float g_WinT[DIN*DD];       // W_in transposed [k][d]
__device__ __align__(16) float g_WcatT[KCAT*GOUT];   // [k][d*4+gate], gate-interleaved
__device__ __align__(16) float g_bias4[GOUT];        // (b_ih+b_hh) gate-interleaved
__device__ __align__(16) int   g_deg[NN];
__device__ __align__(16) float g_degf[NN];
__device__ __align__(16) int   g_rowptr[NN+4];
__device__ __align__(16) int   g_cursor[NN];
__device__ __align__(16) int   g_col[EE];
__device__ __align__(16) int   g_part[128];
__device__ __align__(16) int   g_gptr[BB+4];
__device__ __align__(16) float g_qh[2][BB*KCAT];     // double-buffered [q|r|hh]
__device__ __align__(16) float g_cc[BB*DD];

__device__ __forceinline__ float sigm(float x) { return 1.f / (1.f + expf(-x)); }

// ---------------- fused init: zeroing + weight transposes/permutes ----------
__global__ void k_init(const float* __restrict__ W_in,
                       const float* __restrict__ W_ih,
                       const float* __restrict__ W_hh,
                       const float* __restrict__ b_ih,
                       const float* __restrict__ b_hh) {
    int i = blockIdx.x * blockDim.x + threadIdx.x;   // 1536*256 = 393216 threads
    if (i < NN)          g_deg[i] = 0;
    if (i < 2*BB*KCAT)   (&g_qh[0][0])[i] = 0.f;     // 393216 exactly
    if (i < BB*DD)       g_cc[i] = 0.f;
    if (i < DIN*DD) {
        int k = i >> 7, d = i & (DD-1);
        g_WinT[i] = W_in[d*DIN + k];
    }
    if (i < KCAT*GOUT) {                             // gate-interleaved permutation
        int k = i >> 9, o = i & (GOUT-1);
        int d = o >> 2, gate = o & 3;
        int row = gate*128 + d;
        g_WcatT[i] = (k < 256) ? W_ih[row*256 + k] : W_hh[row*128 + (k - 256)];
    }
    if (i < GOUT) {
        int d = i >> 2, gate = i & 3;
        g_bias4[i] = b_ih[gate*128 + d] + b_hh[gate*128 + d];
    }
}

// ---------------- input layer: h = relu(x @ W_in^T + b_in) ----------------
// tile: 32 nodes x 128 outputs; thread = 4 nodes x 8 outputs (4 LDS / 32 FMA per k)
__global__ __launch_bounds__(128) void k_ingemm(const float* __restrict__ x,
                                                const float* __restrict__ b_in) {
    __shared__ float xs[32*DIN];
    int node0 = blockIdx.x * 32;
    int t = threadIdx.x;
    for (int i = t; i < 32*DIN; i += 128) {
        int node = node0 + i / DIN;
        xs[i] = (node < NN) ? x[node0*DIN + i] : 0.f;
    }
    __syncthreads();
    int tx = t & 15, ty = t >> 4;        // tx: 16 -> 8 outputs each; ty: 8 -> 4 nodes each
    float4 b0 = *(const float4*)(b_in + tx*8);
    float4 b1 = *(const float4*)(b_in + tx*8 + 4);
    float acc[4][8];
    #pragma unroll
    for (int n = 0; n < 4; n++) {
        acc[n][0]=b0.x; acc[n][1]=b0.y; acc[n][2]=b0.z; acc[n][3]=b0.w;
        acc[n][4]=b1.x; acc[n][5]=b1.y; acc[n][6]=b1.z; acc[n][7]=b1.w;
    }
    #pragma unroll 4
    for (int k = 0; k < DIN; k++) {
        float4 w0 = *(const float4*)(g_WinT + k*DD + tx*8);
        float4 w1 = *(const float4*)(g_WinT + k*DD + tx*8 + 4);
        #pragma unroll
        for (int n = 0; n < 4; n++) {
            float xv = xs[(ty*4+n)*DIN + k];
            acc[n][0] += w0.x*xv; acc[n][1] += w0.y*xv;
            acc[n][2] += w0.z*xv; acc[n][3] += w0.w*xv;
            acc[n][4] += w1.x*xv; acc[n][5] += w1.y*xv;
            acc[n][6] += w1.z*xv; acc[n][7] += w1.w*xv;
        }
    }
    #pragma unroll
    for (int n = 0; n < 4; n++) {
        int node = node0 + ty*4 + n;
        if (node < NN) {
            float4 o0, o1;
            o0.x=fmaxf(acc[n][0],0.f); o0.y=fmaxf(acc[n][1],0.f);
            o0.z=fmaxf(acc[n][2],0.f); o0.w=fmaxf(acc[n][3],0.f);
            o1.x=fmaxf(acc[n][4],0.f); o1.y=fmaxf(acc[n][5],0.f);
            o1.z=fmaxf(acc[n][6],0.f); o1.w=fmaxf(acc[n][7],0.f);
            *(float4*)(g_hA + node*DD + tx*8)     = o0;
            *(float4*)(g_hA + node*DD + tx*8 + 4) = o1;
        }
    }
}

// ---------------- CSR build (edge_index / batch are int32) ----------------
__global__ void k_hist(const int* __restrict__ ei) {
    int i = blockIdx.x * blockDim.x + threadIdx.x;
    if (i < EE) atomicAdd(&g_deg[ei[EE + i]], 1);
}

__global__ void k_scan1() {
    __shared__ int s[512];
    int t = threadIdx.x, i = blockIdx.x*512 + t;
    s[t] = (i < NN) ? g_deg[i] : 0;
    __syncthreads();
    for (int o = 256; o > 0; o >>= 1) { if (t < o) s[t] += s[t+o]; __syncthreads(); }
    if (t == 0) g_part[blockIdx.x] = s[0];
}

__global__ void k_scan2() {
    __shared__ int s[128];
    int t = threadIdx.x;
    int v = (t < 98) ? g_part[t] : 0;
    s[t] = v; __syncthreads();
    for (int off = 1; off < 128; off <<= 1) {
        int add = (t >= off) ? s[t-off] : 0;
        __syncthreads();
        s[t] += add;
        __syncthreads();
    }
    g_part[t] = s[t] - v;   // exclusive
}

__global__ void k_scan3() {
    __shared__ int s[512];
    int t = threadIdx.x, i = blockIdx.x*512 + t;
    int cnt = (i < NN) ? g_deg[i] : 0;
    s[t] = cnt; __syncthreads();
    for (int off = 1; off < 512; off <<= 1) {
        int add = (t >= off) ? s[t-off] : 0;
        __syncthreads();
        s[t] += add;
        __syncthreads();
    }
    int excl = s[t] - cnt + g_part[blockIdx.x];
    if (i < NN) {
        g_rowptr[i] = excl;
        g_cursor[i] = excl;
        g_degf[i]   = (float)(cnt > 1 ? cnt : 1);
        if (i == NN-1) g_rowptr[NN] = excl + cnt;
    }
}

__global__ void k_fill(const int* __restrict__ ei) {
    int i = blockIdx.x * blockDim.x + threadIdx.x;
    if (i < EE) {
        int dst = ei[EE + i];
        int p = atomicAdd(&g_cursor[dst], 1);
        g_col[p] = ei[i];
    }
}

__global__ void k_gptr(const int* __restrict__ batch) {
    int n = blockIdx.x * blockDim.x + threadIdx.x;
    if (n >= NN) return;
    int b = batch[n];
    if (n == 0) { for (int q = 0; q <= b; q++) g_gptr[q] = 0; }
    else {
        int bp = batch[n-1];
        for (int q = bp+1; q <= b; q++) g_gptr[q] = n;
    }
    if (n == NN-1) { for (int q = b+1; q <= BB; q++) g_gptr[q] = NN; }
}

// ---------------- one MPNN step: warp per node, float4 per lane ----------------
__global__ __launch_bounds__(128) void k_mpnn(int dir) {
    const float* __restrict__ hin  = dir ? g_hB : g_hA;
    float*       __restrict__ hout = dir ? g_hA : g_hB;
    int gid = blockIdx.x * blockDim.x + threadIdx.x;
    int v = gid >> 5, lane = gid & 31;
    if (v >= NN) return;
    int rs = g_rowptr[v], re = g_rowptr[v+1];
    float ax = 0.f, ay = 0.f, az = 0.f, aw = 0.f;
    int j = rs;
    for (; j + 3 < re; j += 4) {
        int s0 = g_col[j], s1 = g_col[j+1], s2 = g_col[j+2], s3 = g_col[j+3];
        float4 v0 = *(const float4*)(hin + s0*DD + lane*4);
        float4 v1 = *(const float4*)(hin + s1*DD + lane*4);
        float4 v2 = *(const float4*)(hin + s2*DD + lane*4);
        float4 v3 = *(const float4*)(hin + s3*DD + lane*4);
        ax += v0.x + v1.x + v2.x + v3.x;
        ay += v0.y + v1.y + v2.y + v3.y;
        az += v0.z + v1.z + v2.z + v3.z;
        aw += v0.w + v1.w + v2.w + v3.w;
    }
    for (; j < re; j++) {
        int s0 = g_col[j];
        float4 v0 = *(const float4*)(hin + s0*DD + lane*4);
        ax += v0.x; ay += v0.y; az += v0.z; aw += v0.w;
    }
    float inv = 1.f / g_degf[v];
    float4 sf = *(const float4*)(hin + v*DD + lane*4);
    float4 o;
    o.x = (sf.x + ax*inv) * 0.5f;
    o.y = (sf.y + ay*inv) * 0.5f;
    o.z = (sf.z + az*inv) * 0.5f;
    o.w = (sf.w + aw*inv) * 0.5f;
    *(float4*)(hout + v*DD + lane*4) = o;
}

// ---------------- fused gates GEMM + LSTM --------------------------------
// gate-interleaved WcatT: each thread's float4 acc = (i,f,g,o) for one (graph,dim).
// tile: 16 graphs x 32 dims (=128 interleaved outputs); 128 threads; 128 blocks.
__global__ __launch_bounds__(128) void k_gates_lstm(int sin, int sout) {
    __shared__ float qs[16*KCAT];    // 24 KB
    int g0 = (blockIdx.x & 31) * 16;
    int d0 = (blockIdx.x >> 5) * 32;
    const float* __restrict__ QI = g_qh[sin];
    float*       __restrict__ QO = g_qh[sout];
    int t = threadIdx.x;
    for (int i = t; i < 16*KCAT; i += 128) qs[i] = QI[g0*KCAT + i];
    __syncthreads();
    int tx = t & 31, ty = t >> 5;
    int d = d0 + tx;
    float4 bias = *(const float4*)(g_bias4 + d*4);
    float acc[4][4];
    #pragma unroll
    for (int n = 0; n < 4; n++) {
        acc[n][0]=bias.x; acc[n][1]=bias.y; acc[n][2]=bias.z; acc[n][3]=bias.w;
    }
    #pragma unroll 4
    for (int k = 0; k < KCAT; k++) {
        float4 w = *(const float4*)(g_WcatT + k*GOUT + d*4);
        #pragma unroll
        for (int n = 0; n < 4; n++) {
            float xv = qs[(ty*4+n)*KCAT + k];
            acc[n][0] += w.x*xv; acc[n][1] += w.y*xv;
            acc[n][2] += w.z*xv; acc[n][3] += w.w*xv;
        }
    }
    #pragma unroll
    for (int n = 0; n < 4; n++) {
        int b = g0 + ty*4 + n;
        float c = sigm(acc[n][1]) * g_cc[b*DD + d] + sigm(acc[n][0]) * tanhf(acc[n][2]);
        float h = sigm(acc[n][3]) * tanhf(c);
        g_cc[b*DD + d] = c;
        QO[b*KCAT + 256 + d] = h;   // hh
        QO[b*KCAT + d]       = h;   // q slot of q_star
    }
}

// ---------------- single-pass online-softmax attention (+ fused pred) --------
__global__ __launch_bounds__(256) void k_attn(int sel, int last,
                                              const float* __restrict__ Wp,
                                              const float* __restrict__ bp,
                                              float* __restrict__ out) {
    __shared__ __align__(16) float qsm[DD];
    __shared__ __align__(16) float wacc[8][DD];
    __shared__ float wm[8], ws[8], psum[4];
    int b = blockIdx.x, t = threadIdx.x;
    float* __restrict__ Q = g_qh[sel];
    if (t < DD) qsm[t] = Q[b*KCAT + 256 + t];
    __syncthreads();
    int lane = t & 31, w = t >> 5;
    int ns = g_gptr[b], ne = g_gptr[b+1];
    float4 qv = *(const float4*)(qsm + lane*4);
    float m = -INFINITY, s = 0.f;
    float ax = 0.f, ay = 0.f, az = 0.f, aw2 = 0.f;
    for (int n = ns + w*2; n < ne; n += 16) {
        float4 h0 = *(const float4*)(g_hA + n*DD + lane*4);
        float e0 = h0.x*qv.x + h0.y*qv.y + h0.z*qv.z + h0.w*qv.w;
        #pragma unroll
        for (int off = 16; off > 0; off >>= 1) e0 += __shfl_xor_sync(0xffffffffu, e0, off);
        bool has1 = (n + 1 < ne);
        float4 h1 = {0.f,0.f,0.f,0.f};
        float e1 = -INFINITY;
        if (has1) {
            h1 = *(const float4*)(g_hA + (n+1)*DD + lane*4);
            e1 = h1.x*qv.x + h1.y*qv.y + h1.z*qv.z + h1.w*qv.w;
            #pragma unroll
            for (int off = 16; off > 0; off >>= 1) e1 += __shfl_xor_sync(0xffffffffu, e1, off);
        }
        float m2 = fmaxf(m, fmaxf(e0, e1));
        float c  = expf(m - m2);                 // 0 when m was -inf
        float p0 = expf(e0 - m2);
        float p1 = has1 ? expf(e1 - m2) : 0.f;
        s  = s*c + p0 + p1;
        ax = ax*c + p0*h0.x + p1*h1.x;
        ay = ay*c + p0*h0.y + p1*h1.y;
        az = az*c + p0*h0.z + p1*h1.z;
        aw2= aw2*c+ p0*h0.w + p1*h1.w;
        m = m2;
    }
    if (lane == 0) { wm[w] = m; ws[w] = s; }
    float4 av; av.x=ax; av.y=ay; av.z=az; av.w=aw2;
    *(float4*)(&wacc[w][lane*4]) = av;
    __syncthreads();
    if (t < DD) {
        float r = 0.f;
        if (ne > ns) {
            float M = wm[0];
            #pragma unroll
            for (int i = 1; i < 8; i++) M = fmaxf(M, wm[i]);
            float denom = 1e-16f, num = 0.f;
            #pragma unroll
            for (int i = 0; i < 8; i++) {
                float sc = expf(wm[i] - M);
                denom += sc * ws[i];
                num   += sc * wacc[i][t];
            }
            r = num / denom;
        }
        Q[b*KCAT + DD + t] = r;     // r slot of q_star
        if (last) {
            float part = qsm[t]*Wp[t] + r*Wp[DD + t];
            #pragma unroll
            for (int off = 16; off > 0; off >>= 1) part += __shfl_xor_sync(0xffffffffu, part, off);
            if (lane == 0) psum[t >> 5] = part;
        }
    }
    __syncthreads();
    if (last && t == 0) out[b] = psum[0] + psum[1] + psum[2] + psum[3] + bp[0];
}

// ---------------- launch ----------------
extern "C" void kernel_launch(void* const* d_in, const int* in_sizes, int n_in,
                              void* d_out, int out_size) {
    const float *x=0, *W_in=0, *b_in=0, *W_ih=0, *W_hh=0, *b_ih=0, *b_hh=0, *W_pred=0, *b_pred=0;
    const int *ei=0, *batch=0;
    for (int i = 0; i < n_in; i++) {
        int s = in_sizes[i];
        const void* p = d_in[i];
        switch (s) {
            case 4800000: x      = (const float*)p; break;
            case 1600000: ei     = (const int*)p;   break;
            case 50000:   batch  = (const int*)p;   break;
            case 12288:   W_in   = (const float*)p; break;
            case 128:     b_in   = (const float*)p; break;
            case 131072:  W_ih   = (const float*)p; break;
            case 65536:   W_hh   = (const float*)p; break;
            case 512:     if (!b_ih) b_ih = (const float*)p; else b_hh = (const float*)p; break;
            case 256:     W_pred = (const float*)p; break;
            case 1:       b_pred = (const float*)p; break;
            default: break;
        }
    }
    float* out = (float*)d_out;
    (void)out_size;

    k_init<<<1536, 256>>>(W_in, W_ih, W_hh, b_ih, b_hh);   // 393216 threads
    k_ingemm<<<(NN + 31)/32, 128>>>(x, b_in);
    k_hist<<<(EE + 255)/256, 256>>>(ei);
    k_scan1<<<98, 512>>>();
    k_scan2<<<1, 128>>>();
    k_scan3<<<98, 512>>>();
    k_fill<<<(EE + 255)/256, 256>>>(ei);
    k_gptr<<<(NN + 255)/256, 256>>>(batch);

    k_mpnn<<<(NN*32 + 127)/128, 128>>>(0);        // hA -> hB
    k_mpnn<<<(NN*32 + 127)/128, 128>>>(1);        // hB -> hA
    k_mpnn<<<(NN*32 + 127)/128, 128>>>(0);        // hA -> hB
    k_mpnn<<<(NN*32 + 127)/128, 128>>>(1);        // hB -> hA  (final h in g_hA)

    for (int s = 0; s < 3; s++) {
        int sin = s & 1, sout = (s + 1) & 1;
        k_gates_lstm<<<128, 128>>>(sin, sout);
        k_attn<<<BB, 256>>>(sout, (s == 2) ? 1 : 0, W_pred, b_pred, out);
    }
}

// round 14
// speedup vs baseline: 1.2119x; 1.1895x over previous
#include <cuda_runtime.h>
#include <cuda_fp16.h>
#include <math.h>

#define NN   50000
#define EE   800000
#define DIN  96
#define DD   128
#define BB   512
#define KCAT 384
#define GOUT 512

// ---------------- scratch (static device globals; no allocs) ----------------
__device__ __align__(16) __half g_h16A[NN*DD];       // 12.8 MB (fp16 node features)
__device__ __align__(16) __half g_h16B[NN*DD];       // 12.8 MB
__device__ __align__(16) float g_WinT[DIN*DD];       // W_in transposed [k][d]
__device__ __align__(16) float g_WcatT[KCAT*GOUT];   // [k][d*4+gate], gate-interleaved
__device__ __align__(16) float g_bias4[GOUT];        // (b_ih+b_hh) gate-interleaved
__device__ __align__(16) int   g_deg[NN];
__device__ __align__(16) float g_degf[NN];
__device__ __align__(16) int   g_rowptr[NN+4];
__device__ __align__(16) int   g_cursor[NN];
__device__ __align__(16) int   g_col[EE];
__device__ __align__(16) int   g_part[128];
__device__ __align__(16) int   g_gptr[BB+4];
__device__ __align__(16) float g_qh[2][BB*KCAT];     // double-buffered [q|r|hh]
__device__ __align__(16) float g_cc[BB*DD];

__device__ __forceinline__ float sigm(float x) { return 1.f / (1.f + expf(-x)); }

// unpack 4 halves (as uint2) -> 4 floats
__device__ __forceinline__ void h4_to_f4(uint2 u, float& a, float& b, float& c, float& d) {
    __half2 h0 = *(__half2*)&u.x, h1 = *(__half2*)&u.y;
    float2 f0 = __half22float2(h0), f1 = __half22float2(h1);
    a = f0.x; b = f0.y; c = f1.x; d = f1.y;
}

// ---------------- fused init: zeroing + weight transposes/permutes ----------
__global__ void k_init(const float* __restrict__ W_in,
                       const float* __restrict__ W_ih,
                       const float* __restrict__ W_hh,
                       const float* __restrict__ b_ih,
                       const float* __restrict__ b_hh) {
    int i = blockIdx.x * blockDim.x + threadIdx.x;   // 1536*256 = 393216 threads
    if (i < NN)          g_deg[i] = 0;
    if (i < 2*BB*KCAT)   (&g_qh[0][0])[i] = 0.f;     // 393216 exactly
    if (i < BB*DD)       g_cc[i] = 0.f;
    if (i < DIN*DD) {
        int k = i >> 7, d = i & (DD-1);
        g_WinT[i] = W_in[d*DIN + k];
    }
    if (i < KCAT*GOUT) {                             // gate-interleaved permutation
        int k = i >> 9, o = i & (GOUT-1);
        int d = o >> 2, gate = o & 3;
        int row = gate*128 + d;
        g_WcatT[i] = (k < 256) ? W_ih[row*256 + k] : W_hh[row*128 + (k - 256)];
    }
    if (i < GOUT) {
        int d = i >> 2, gate = i & 3;
        g_bias4[i] = b_ih[gate*128 + d] + b_hh[gate*128 + d];
    }
}

// ---------------- input layer: h = relu(x @ W_in^T + b_in), fp16 out ---------
__global__ __launch_bounds__(128) void k_ingemm(const float* __restrict__ x,
                                                const float* __restrict__ b_in) {
    __shared__ float xs[32*DIN];
    int node0 = blockIdx.x * 32;
    int t = threadIdx.x;
    for (int i = t; i < 32*DIN; i += 128) {
        int node = node0 + i / DIN;
        xs[i] = (node < NN) ? x[node0*DIN + i] : 0.f;
    }
    __syncthreads();
    int tx = t & 15, ty = t >> 4;        // tx: 16 -> 8 outputs; ty: 8 -> 4 nodes
    float4 b0 = *(const float4*)(b_in + tx*8);
    float4 b1 = *(const float4*)(b_in + tx*8 + 4);
    float acc[4][8];
    #pragma unroll
    for (int n = 0; n < 4; n++) {
        acc[n][0]=b0.x; acc[n][1]=b0.y; acc[n][2]=b0.z; acc[n][3]=b0.w;
        acc[n][4]=b1.x; acc[n][5]=b1.y; acc[n][6]=b1.z; acc[n][7]=b1.w;
    }
    #pragma unroll 4
    for (int k = 0; k < DIN; k++) {
        float4 w0 = *(const float4*)(g_WinT + k*DD + tx*8);
        float4 w1 = *(const float4*)(g_WinT + k*DD + tx*8 + 4);
        #pragma unroll
        for (int n = 0; n < 4; n++) {
            float xv = xs[(ty*4+n)*DIN + k];
            acc[n][0] += w0.x*xv; acc[n][1] += w0.y*xv;
            acc[n][2] += w0.z*xv; acc[n][3] += w0.w*xv;
            acc[n][4] += w1.x*xv; acc[n][5] += w1.y*xv;
            acc[n][6] += w1.z*xv; acc[n][7] += w1.w*xv;
        }
    }
    #pragma unroll
    for (int n = 0; n < 4; n++) {
        int node = node0 + ty*4 + n;
        if (node < NN) {
            __half2 p0 = __floats2half2_rn(fmaxf(acc[n][0],0.f), fmaxf(acc[n][1],0.f));
            __half2 p1 = __floats2half2_rn(fmaxf(acc[n][2],0.f), fmaxf(acc[n][3],0.f));
            __half2 p2 = __floats2half2_rn(fmaxf(acc[n][4],0.f), fmaxf(acc[n][5],0.f));
            __half2 p3 = __floats2half2_rn(fmaxf(acc[n][6],0.f), fmaxf(acc[n][7],0.f));
            uint4 u;
            u.x = *(unsigned*)&p0; u.y = *(unsigned*)&p1;
            u.z = *(unsigned*)&p2; u.w = *(unsigned*)&p3;
            *(uint4*)(g_h16A + node*DD + tx*8) = u;   // 16B store, 8 halves
        }
    }
}

// ---------------- CSR build (edge_index / batch are int32) ----------------
__global__ void k_hist(const int* __restrict__ ei) {
    int i = blockIdx.x * blockDim.x + threadIdx.x;
    if (i < EE) atomicAdd(&g_deg[ei[EE + i]], 1);
}

__global__ void k_scan1() {
    __shared__ int s[512];
    int t = threadIdx.x, i = blockIdx.x*512 + t;
    s[t] = (i < NN) ? g_deg[i] : 0;
    __syncthreads();
    for (int o = 256; o > 0; o >>= 1) { if (t < o) s[t] += s[t+o]; __syncthreads(); }
    if (t == 0) g_part[blockIdx.x] = s[0];
}

__global__ void k_scan2() {
    __shared__ int s[128];
    int t = threadIdx.x;
    int v = (t < 98) ? g_part[t] : 0;
    s[t] = v; __syncthreads();
    for (int off = 1; off < 128; off <<= 1) {
        int add = (t >= off) ? s[t-off] : 0;
        __syncthreads();
        s[t] += add;
        __syncthreads();
    }
    g_part[t] = s[t] - v;   // exclusive
}

__global__ void k_scan3() {
    __shared__ int s[512];
    int t = threadIdx.x, i = blockIdx.x*512 + t;
    int cnt = (i < NN) ? g_deg[i] : 0;
    s[t] = cnt; __syncthreads();
    for (int off = 1; off < 512; off <<= 1) {
        int add = (t >= off) ? s[t-off] : 0;
        __syncthreads();
        s[t] += add;
        __syncthreads();
    }
    int excl = s[t] - cnt + g_part[blockIdx.x];
    if (i < NN) {
        g_rowptr[i] = excl;
        g_cursor[i] = excl;
        g_degf[i]   = (float)(cnt > 1 ? cnt : 1);
        if (i == NN-1) g_rowptr[NN] = excl + cnt;
    }
}

__global__ void k_fill(const int* __restrict__ ei) {
    int i = blockIdx.x * blockDim.x + threadIdx.x;
    if (i < EE) {
        int dst = ei[EE + i];
        int p = atomicAdd(&g_cursor[dst], 1);
        g_col[p] = ei[i];
    }
}

__global__ void k_gptr(const int* __restrict__ batch) {
    int n = blockIdx.x * blockDim.x + threadIdx.x;
    if (n >= NN) return;
    int b = batch[n];
    if (n == 0) { for (int q = 0; q <= b; q++) g_gptr[q] = 0; }
    else {
        int bp = batch[n-1];
        for (int q = bp+1; q <= b; q++) g_gptr[q] = n;
    }
    if (n == NN-1) { for (int q = b+1; q <= BB; q++) g_gptr[q] = NN; }
}

// ---------------- one MPNN step: warp per node, 4 dims (uint2) per lane ------
__global__ __launch_bounds__(128) void k_mpnn(int dir) {
    const __half* __restrict__ hin  = dir ? g_h16B : g_h16A;
    __half*       __restrict__ hout = dir ? g_h16A : g_h16B;
    int gid = blockIdx.x * blockDim.x + threadIdx.x;
    int v = gid >> 5, lane = gid & 31;
    if (v >= NN) return;
    int base = lane*4;
    int rs = g_rowptr[v], re = g_rowptr[v+1];
    float ax = 0.f, ay = 0.f, az = 0.f, aw = 0.f;
    int j = rs;
    for (; j + 3 < re; j += 4) {
        int s0 = g_col[j], s1 = g_col[j+1], s2 = g_col[j+2], s3 = g_col[j+3];
        uint2 u0 = *(const uint2*)(hin + s0*DD + base);
        uint2 u1 = *(const uint2*)(hin + s1*DD + base);
        uint2 u2 = *(const uint2*)(hin + s2*DD + base);
        uint2 u3 = *(const uint2*)(hin + s3*DD + base);
        float a,b,c,d;
        h4_to_f4(u0,a,b,c,d); ax+=a; ay+=b; az+=c; aw+=d;
        h4_to_f4(u1,a,b,c,d); ax+=a; ay+=b; az+=c; aw+=d;
        h4_to_f4(u2,a,b,c,d); ax+=a; ay+=b; az+=c; aw+=d;
        h4_to_f4(u3,a,b,c,d); ax+=a; ay+=b; az+=c; aw+=d;
    }
    for (; j < re; j++) {
        uint2 u0 = *(const uint2*)(hin + g_col[j]*DD + base);
        float a,b,c,d;
        h4_to_f4(u0,a,b,c,d); ax+=a; ay+=b; az+=c; aw+=d;
    }
    float inv = 1.f / g_degf[v];
    uint2 us = *(const uint2*)(hin + v*DD + base);
    float sx,sy,sz,sw;
    h4_to_f4(us,sx,sy,sz,sw);
    float ox = (sx + ax*inv) * 0.5f;
    float oy = (sy + ay*inv) * 0.5f;
    float oz = (sz + az*inv) * 0.5f;
    float ow = (sw + aw*inv) * 0.5f;
    __half2 o0 = __floats2half2_rn(ox, oy);
    __half2 o1 = __floats2half2_rn(oz, ow);
    uint2 uo; uo.x = *(unsigned*)&o0; uo.y = *(unsigned*)&o1;
    *(uint2*)(hout + v*DD + base) = uo;
}

// ---------------- fused gates GEMM + LSTM --------------------------------
__global__ __launch_bounds__(128) void k_gates_lstm(int sin, int sout) {
    __shared__ float qs[16*KCAT];    // 24 KB
    int g0 = (blockIdx.x & 31) * 16;
    int d0 = (blockIdx.x >> 5) * 32;
    const float* __restrict__ QI = g_qh[sin];
    float*       __restrict__ QO = g_qh[sout];
    int t = threadIdx.x;
    for (int i = t; i < 16*KCAT; i += 128) qs[i] = QI[g0*KCAT + i];
    __syncthreads();
    int tx = t & 31, ty = t >> 5;
    int d = d0 + tx;
    float4 bias = *(const float4*)(g_bias4 + d*4);
    float acc[4][4];
    #pragma unroll
    for (int n = 0; n < 4; n++) {
        acc[n][0]=bias.x; acc[n][1]=bias.y; acc[n][2]=bias.z; acc[n][3]=bias.w;
    }
    #pragma unroll 4
    for (int k = 0; k < KCAT; k++) {
        float4 w = *(const float4*)(g_WcatT + k*GOUT + d*4);
        #pragma unroll
        for (int n = 0; n < 4; n++) {
            float xv = qs[(ty*4+n)*KCAT + k];
            acc[n][0] += w.x*xv; acc[n][1] += w.y*xv;
            acc[n][2] += w.z*xv; acc[n][3] += w.w*xv;
        }
    }
    #pragma unroll
    for (int n = 0; n < 4; n++) {
        int b = g0 + ty*4 + n;
        float c = sigm(acc[n][1]) * g_cc[b*DD + d] + sigm(acc[n][0]) * tanhf(acc[n][2]);
        float h = sigm(acc[n][3]) * tanhf(c);
        g_cc[b*DD + d] = c;
        QO[b*KCAT + 256 + d] = h;   // hh
        QO[b*KCAT + d]       = h;   // q slot of q_star
    }
}

// ---------------- single-pass online-softmax attention (+ fused pred) --------
__global__ __launch_bounds__(256) void k_attn(int sel, int last,
                                              const float* __restrict__ Wp,
                                              const float* __restrict__ bp,
                                              float* __restrict__ out) {
    __shared__ __align__(16) float qsm[DD];
    __shared__ __align__(16) float wacc[8][DD];
    __shared__ float wm[8], ws[8], psum[4];
    int b = blockIdx.x, t = threadIdx.x;
    float* __restrict__ Q = g_qh[sel];
    if (t < DD) qsm[t] = Q[b*KCAT + 256 + t];
    __syncthreads();
    int lane = t & 31, w = t >> 5;
    int base = lane*4;
    int ns = g_gptr[b], ne = g_gptr[b+1];
    float4 qv = *(const float4*)(qsm + base);
    float m = -INFINITY, s = 0.f;
    float ax = 0.f, ay = 0.f, az = 0.f, aw2 = 0.f;
    for (int n = ns + w*2; n < ne; n += 16) {
        float h0x,h0y,h0z,h0w;
        h4_to_f4(*(const uint2*)(g_h16A + n*DD + base), h0x,h0y,h0z,h0w);
        float e0 = h0x*qv.x + h0y*qv.y + h0z*qv.z + h0w*qv.w;
        #pragma unroll
        for (int off = 16; off > 0; off >>= 1) e0 += __shfl_xor_sync(0xffffffffu, e0, off);
        bool has1 = (n + 1 < ne);
        float h1x=0.f,h1y=0.f,h1z=0.f,h1w=0.f;
        float e1 = -INFINITY;
        if (has1) {
            h4_to_f4(*(const uint2*)(g_h16A + (n+1)*DD + base), h1x,h1y,h1z,h1w);
            e1 = h1x*qv.x + h1y*qv.y + h1z*qv.z + h1w*qv.w;
            #pragma unroll
            for (int off = 16; off > 0; off >>= 1) e1 += __shfl_xor_sync(0xffffffffu, e1, off);
        }
        float m2 = fmaxf(m, fmaxf(e0, e1));
        float c  = expf(m - m2);                 // 0 when m was -inf
        float p0 = expf(e0 - m2);
        float p1 = has1 ? expf(e1 - m2) : 0.f;
        s  = s*c + p0 + p1;
        ax = ax*c + p0*h0x + p1*h1x;
        ay = ay*c + p0*h0y + p1*h1y;
        az = az*c + p0*h0z + p1*h1z;
        aw2= aw2*c+ p0*h0w + p1*h1w;
        m = m2;
    }
    if (lane == 0) { wm[w] = m; ws[w] = s; }
    float4 av; av.x=ax; av.y=ay; av.z=az; av.w=aw2;
    *(float4*)(&wacc[w][base]) = av;
    __syncthreads();
    if (t < DD) {
        float r = 0.f;
        if (ne > ns) {
            float M = wm[0];
            #pragma unroll
            for (int i = 1; i < 8; i++) M = fmaxf(M, wm[i]);
            float denom = 1e-16f, num = 0.f;
            #pragma unroll
            for (int i = 0; i < 8; i++) {
                float sc = expf(wm[i] - M);
                denom += sc * ws[i];
                num   += sc * wacc[i][t];
            }
            r = num / denom;
        }
        Q[b*KCAT + DD + t] = r;     // r slot of q_star
        if (last) {
            float part = qsm[t]*Wp[t] + r*Wp[DD + t];
            #pragma unroll
            for (int off = 16; off > 0; off >>= 1) part += __shfl_xor_sync(0xffffffffu, part, off);
            if (lane == 0) psum[t >> 5] = part;
        }
    }
    __syncthreads();
    if (last && t == 0) out[b] = psum[0] + psum[1] + psum[2] + psum[3] + bp[0];
}

// ---------------- launch ----------------
extern "C" void kernel_launch(void* const* d_in, const int* in_sizes, int n_in,
                              void* d_out, int out_size) {
    const float *x=0, *W_in=0, *b_in=0, *W_ih=0, *W_hh=0, *b_ih=0, *b_hh=0, *W_pred=0, *b_pred=0;
    const int *ei=0, *batch=0;
    for (int i = 0; i < n_in; i++) {
        int s = in_sizes[i];
        const void* p = d_in[i];
        switch (s) {
            case 4800000: x      = (const float*)p; break;
            case 1600000: ei     = (const int*)p;   break;
            case 50000:   batch  = (const int*)p;   break;
            case 12288:   W_in   = (const float*)p; break;
            case 128:     b_in   = (const float*)p; break;
            case 131072:  W_ih   = (const float*)p; break;
            case 65536:   W_hh   = (const float*)p; break;
            case 512:     if (!b_ih) b_ih = (const float*)p; else b_hh = (const float*)p; break;
            case 256:     W_pred = (const float*)p; break;
            case 1:       b_pred = (const float*)p; break;
            default: break;
        }
    }
    float* out = (float*)d_out;
    (void)out_size;

    k_init<<<1536, 256>>>(W_in, W_ih, W_hh, b_ih, b_hh);   // 393216 threads
    k_ingemm<<<(NN + 31)/32, 128>>>(x, b_in);
    k_hist<<<(EE + 255)/256, 256>>>(ei);
    k_scan1<<<98, 512>>>();
    k_scan2<<<1, 128>>>();
    k_scan3<<<98, 512>>>();
    k_fill<<<(EE + 255)/256, 256>>>(ei);
    k_gptr<<<(NN + 255)/256, 256>>>(batch);

    k_mpnn<<<(NN*32 + 127)/128, 128>>>(0);        // A -> B
    k_mpnn<<<(NN*32 + 127)/128, 128>>>(1);        // B -> A
    k_mpnn<<<(NN*32 + 127)/128, 128>>>(0);        // A -> B
    k_mpnn<<<(NN*32 + 127)/128, 128>>>(1);        // B -> A  (final h in g_h16A)

    for (int s = 0; s < 3; s++) {
        int sin = s & 1, sout = (s + 1) & 1;
        k_gates_lstm<<<128, 128>>>(sin, sout);
        k_attn<<<BB, 256>>>(sout, (s == 2) ? 1 : 0, W_pred, b_pred, out);
    }
}

// round 15
// speedup vs baseline: 1.2655x; 1.0442x over previous
#include <cuda_runtime.h>
#include <cuda_fp16.h>
#include <math.h>

#define NN   50000
#define EE   800000
#define DIN  96
#define DD   128
#define BB   512
#define KCAT 384
#define GOUT 512
#define NB_GEMM 1563          // ingemm blocks (32 nodes each)
#define NB_HIST 1563          // hist blocks (512 edges each)

// ---------------- scratch (static device globals; no allocs) ----------------
__device__ __align__(16) __half g_h16A[NN*DD];       // 12.8 MB
__device__ __align__(16) __half g_h16B[NN*DD];       // 12.8 MB
__device__ __align__(16) float g_WinT[DIN*DD];
__device__ __align__(16) float g_WcatT[KCAT*GOUT];   // [k][d*4+gate]
__device__ __align__(16) float g_bias4[GOUT];
__device__ __align__(16) int   g_deg[NN];
__device__ __align__(16) float g_degf[NN];
__device__ __align__(16) int   g_rowptr[NN+4];
__device__ __align__(16) int   g_cursor[NN];
__device__ __align__(16) int   g_col[EE];
__device__ __align__(16) int   g_part[128];
__device__ __align__(16) int   g_gptr[BB+4];
__device__ __align__(16) float g_qh[2][BB*KCAT];
__device__ __align__(16) float g_cc[BB*DD];

__device__ __forceinline__ float sigm(float x) { return 1.f / (1.f + expf(-x)); }

__device__ __forceinline__ void h4_to_f4(uint2 u, float& a, float& b, float& c, float& d) {
    __half2 h0 = *(__half2*)&u.x, h1 = *(__half2*)&u.y;
    float2 f0 = __half22float2(h0), f1 = __half22float2(h1);
    a = f0.x; b = f0.y; c = f1.x; d = f1.y;
}

// ---------------- fused init ----------------
__global__ void k_init(const float* __restrict__ W_in,
                       const float* __restrict__ W_ih,
                       const float* __restrict__ W_hh,
                       const float* __restrict__ b_ih,
                       const float* __restrict__ b_hh) {
    int i = blockIdx.x * blockDim.x + threadIdx.x;   // 1536*256 = 393216
    if (i < NN)          g_deg[i] = 0;
    if (i < 2*BB*KCAT)   (&g_qh[0][0])[i] = 0.f;
    if (i < BB*DD)       g_cc[i] = 0.f;
    if (i < DIN*DD) {
        int k = i >> 7, d = i & (DD-1);
        g_WinT[i] = W_in[d*DIN + k];
    }
    if (i < KCAT*GOUT) {
        int k = i >> 9, o = i & (GOUT-1);
        int d = o >> 2, gate = o & 3;
        int row = gate*128 + d;
        g_WcatT[i] = (k < 256) ? W_ih[row*256 + k] : W_hh[row*128 + (k - 256)];
    }
    if (i < GOUT) {
        int d = i >> 2, gate = i & 3;
        g_bias4[i] = b_ih[gate*128 + d] + b_hh[gate*128 + d];
    }
}

// ------- fused: input GEMM (blocks 0..NB_GEMM-1) + degree hist (rest) --------
__global__ __launch_bounds__(128) void k_ingemm_hist(const float* __restrict__ x,
                                                     const float* __restrict__ b_in,
                                                     const int* __restrict__ ei) {
    __shared__ float xs[32*DIN];
    int t = threadIdx.x;
    if (blockIdx.x >= NB_GEMM) {
        // histogram of dst degrees: 512 edges per block
        int base = (blockIdx.x - NB_GEMM) * 512 + t;
        #pragma unroll
        for (int j = 0; j < 4; j++) {
            int idx = base + j*128;
            if (idx < EE) atomicAdd(&g_deg[ei[EE + idx]], 1);
        }
        return;
    }
    int node0 = blockIdx.x * 32;
    for (int i = t; i < 32*DIN; i += 128) {
        int node = node0 + i / DIN;
        xs[i] = (node < NN) ? x[node0*DIN + i] : 0.f;
    }
    __syncthreads();
    int tx = t & 15, ty = t >> 4;
    float4 b0 = *(const float4*)(b_in + tx*8);
    float4 b1 = *(const float4*)(b_in + tx*8 + 4);
    float acc[4][8];
    #pragma unroll
    for (int n = 0; n < 4; n++) {
        acc[n][0]=b0.x; acc[n][1]=b0.y; acc[n][2]=b0.z; acc[n][3]=b0.w;
        acc[n][4]=b1.x; acc[n][5]=b1.y; acc[n][6]=b1.z; acc[n][7]=b1.w;
    }
    #pragma unroll 4
    for (int k = 0; k < DIN; k++) {
        float4 w0 = *(const float4*)(g_WinT + k*DD + tx*8);
        float4 w1 = *(const float4*)(g_WinT + k*DD + tx*8 + 4);
        #pragma unroll
        for (int n = 0; n < 4; n++) {
            float xv = xs[(ty*4+n)*DIN + k];
            acc[n][0] += w0.x*xv; acc[n][1] += w0.y*xv;
            acc[n][2] += w0.z*xv; acc[n][3] += w0.w*xv;
            acc[n][4] += w1.x*xv; acc[n][5] += w1.y*xv;
            acc[n][6] += w1.z*xv; acc[n][7] += w1.w*xv;
        }
    }
    #pragma unroll
    for (int n = 0; n < 4; n++) {
        int node = node0 + ty*4 + n;
        if (node < NN) {
            __half2 p0 = __floats2half2_rn(fmaxf(acc[n][0],0.f), fmaxf(acc[n][1],0.f));
            __half2 p1 = __floats2half2_rn(fmaxf(acc[n][2],0.f), fmaxf(acc[n][3],0.f));
            __half2 p2 = __floats2half2_rn(fmaxf(acc[n][4],0.f), fmaxf(acc[n][5],0.f));
            __half2 p3 = __floats2half2_rn(fmaxf(acc[n][6],0.f), fmaxf(acc[n][7],0.f));
            uint4 u;
            u.x = *(unsigned*)&p0; u.y = *(unsigned*)&p1;
            u.z = *(unsigned*)&p2; u.w = *(unsigned*)&p3;
            *(uint4*)(g_h16A + node*DD + tx*8) = u;
        }
    }
}

// ---------------- scan1: per-block reduce of deg (shuffle) ----------------
__global__ void k_scan1() {
    __shared__ int wsum[16];
    int t = threadIdx.x, i = blockIdx.x*512 + t;
    int v = (i < NN) ? g_deg[i] : 0;
    #pragma unroll
    for (int off = 16; off > 0; off >>= 1) v += __shfl_xor_sync(0xffffffffu, v, off);
    int lane = t & 31, w = t >> 5;
    if (lane == 0) wsum[w] = v;
    __syncthreads();
    if (w == 0) {
        int s = (lane < 16) ? wsum[lane] : 0;
        #pragma unroll
        for (int off = 8; off > 0; off >>= 1) s += __shfl_xor_sync(0xffffffffu, s, off);
        if (lane == 0) g_part[blockIdx.x] = s;
    }
}

// ---------------- scan2: exclusive scan of 98 partials (shuffle) -------------
__global__ void k_scan2() {
    __shared__ int wsum[4];
    int t = threadIdx.x;                      // 128 threads
    int lane = t & 31, w = t >> 5;
    int v = (t < 98) ? g_part[t] : 0;
    int s = v;
    #pragma unroll
    for (int off = 1; off < 32; off <<= 1) {
        int y = __shfl_up_sync(0xffffffffu, s, off);
        if (lane >= off) s += y;
    }
    if (lane == 31) wsum[w] = s;
    __syncthreads();
    int pre = 0;
    #pragma unroll
    for (int i = 0; i < 4; i++) if (i < w) pre += wsum[i];
    g_part[t] = s - v + pre;                  // exclusive
}

// ------- scan3 (shuffle) + rowptr/cursor/degf + fused gptr -------------------
__global__ void k_scan3_gptr(const int* __restrict__ batch) {
    __shared__ int wsum[16];
    int t = threadIdx.x, i = blockIdx.x*512 + t;
    int lane = t & 31, w = t >> 5;
    int cnt = (i < NN) ? g_deg[i] : 0;
    int s = cnt;
    #pragma unroll
    for (int off = 1; off < 32; off <<= 1) {
        int y = __shfl_up_sync(0xffffffffu, s, off);
        if (lane >= off) s += y;
    }
    if (lane == 31) wsum[w] = s;
    __syncthreads();
    if (w == 0) {
        int ws = (lane < 16) ? wsum[lane] : 0;
        #pragma unroll
        for (int off = 1; off < 16; off <<= 1) {
            int y = __shfl_up_sync(0xffffffffu, ws, off);
            if (lane >= off) ws += y;
        }
        if (lane < 16) wsum[lane] = ws;       // inclusive warp prefix
    }
    __syncthreads();
    int excl = s - cnt + (w > 0 ? wsum[w-1] : 0) + g_part[blockIdx.x];
    if (i < NN) {
        g_rowptr[i] = excl;
        g_cursor[i] = excl;
        g_degf[i]   = (float)(cnt > 1 ? cnt : 1);
        if (i == NN-1) g_rowptr[NN] = excl + cnt;
    }
    // fused gptr (independent of scan results; batch is sorted)
    if (i < NN) {
        int b = batch[i];
        if (i == 0) { for (int q = 0; q <= b; q++) g_gptr[q] = 0; }
        else {
            int bp = batch[i-1];
            for (int q = bp+1; q <= b; q++) g_gptr[q] = i;
        }
        if (i == NN-1) { for (int q = b+1; q <= BB; q++) g_gptr[q] = NN; }
    }
}

__global__ void k_fill(const int* __restrict__ ei) {
    int i = blockIdx.x * blockDim.x + threadIdx.x;
    if (i < EE) {
        int dst = ei[EE + i];
        int p = atomicAdd(&g_cursor[dst], 1);
        g_col[p] = ei[i];
    }
}

// ---------------- one MPNN step: warp per node, unroll 8 ----------------
__global__ __launch_bounds__(128) void k_mpnn(int dir) {
    const __half* __restrict__ hin  = dir ? g_h16B : g_h16A;
    __half*       __restrict__ hout = dir ? g_h16A : g_h16B;
    int gid = blockIdx.x * blockDim.x + threadIdx.x;
    int v = gid >> 5, lane = gid & 31;
    if (v >= NN) return;
    int base = lane*4;
    int rs = g_rowptr[v], re = g_rowptr[v+1];
    float ax = 0.f, ay = 0.f, az = 0.f, aw = 0.f;
    int j = rs;
    for (; j + 7 < re; j += 8) {
        uint2 u0 = *(const uint2*)(hin + g_col[j  ]*DD + base);
        uint2 u1 = *(const uint2*)(hin + g_col[j+1]*DD + base);
        uint2 u2 = *(const uint2*)(hin + g_col[j+2]*DD + base);
        uint2 u3 = *(const uint2*)(hin + g_col[j+3]*DD + base);
        uint2 u4 = *(const uint2*)(hin + g_col[j+4]*DD + base);
        uint2 u5 = *(const uint2*)(hin + g_col[j+5]*DD + base);
        uint2 u6 = *(const uint2*)(hin + g_col[j+6]*DD + base);
        uint2 u7 = *(const uint2*)(hin + g_col[j+7]*DD + base);
        float a,b,c,d;
        h4_to_f4(u0,a,b,c,d); ax+=a; ay+=b; az+=c; aw+=d;
        h4_to_f4(u1,a,b,c,d); ax+=a; ay+=b; az+=c; aw+=d;
        h4_to_f4(u2,a,b,c,d); ax+=a; ay+=b; az+=c; aw+=d;
        h4_to_f4(u3,a,b,c,d); ax+=a; ay+=b; az+=c; aw+=d;
        h4_to_f4(u4,a,b,c,d); ax+=a; ay+=b; az+=c; aw+=d;
        h4_to_f4(u5,a,b,c,d); ax+=a; ay+=b; az+=c; aw+=d;
        h4_to_f4(u6,a,b,c,d); ax+=a; ay+=b; az+=c; aw+=d;
        h4_to_f4(u7,a,b,c,d); ax+=a; ay+=b; az+=c; aw+=d;
    }
    for (; j < re; j++) {
        uint2 u0 = *(const uint2*)(hin + g_col[j]*DD + base);
        float a,b,c,d;
        h4_to_f4(u0,a,b,c,d); ax+=a; ay+=b; az+=c; aw+=d;
    }
    float inv = 1.f / g_degf[v];
    uint2 us = *(const uint2*)(hin + v*DD + base);
    float sx,sy,sz,sw;
    h4_to_f4(us,sx,sy,sz,sw);
    __half2 o0 = __floats2half2_rn((sx + ax*inv)*0.5f, (sy + ay*inv)*0.5f);
    __half2 o1 = __floats2half2_rn((sz + az*inv)*0.5f, (sw + aw*inv)*0.5f);
    uint2 uo; uo.x = *(unsigned*)&o0; uo.y = *(unsigned*)&o1;
    *(uint2*)(hout + v*DD + base) = uo;
}

// ---------------- fused gates GEMM + LSTM --------------------------------
__global__ __launch_bounds__(128) void k_gates_lstm(int sin, int sout) {
    __shared__ float qs[16*KCAT];
    int g0 = (blockIdx.x & 31) * 16;
    int d0 = (blockIdx.x >> 5) * 32;
    const float* __restrict__ QI = g_qh[sin];
    float*       __restrict__ QO = g_qh[sout];
    int t = threadIdx.x;
    for (int i = t; i < 16*KCAT; i += 128) qs[i] = QI[g0*KCAT + i];
    __syncthreads();
    int tx = t & 31, ty = t >> 5;
    int d = d0 + tx;
    float4 bias = *(const float4*)(g_bias4 + d*4);
    float acc[4][4];
    #pragma unroll
    for (int n = 0; n < 4; n++) {
        acc[n][0]=bias.x; acc[n][1]=bias.y; acc[n][2]=bias.z; acc[n][3]=bias.w;
    }
    #pragma unroll 4
    for (int k = 0; k < KCAT; k++) {
        float4 w = *(const float4*)(g_WcatT + k*GOUT + d*4);
        #pragma unroll
        for (int n = 0; n < 4; n++) {
            float xv = qs[(ty*4+n)*KCAT + k];
            acc[n][0] += w.x*xv; acc[n][1] += w.y*xv;
            acc[n][2] += w.z*xv; acc[n][3] += w.w*xv;
        }
    }
    #pragma unroll
    for (int n = 0; n < 4; n++) {
        int b = g0 + ty*4 + n;
        float c = sigm(acc[n][1]) * g_cc[b*DD + d] + sigm(acc[n][0]) * tanhf(acc[n][2]);
        float h = sigm(acc[n][3]) * tanhf(c);
        g_cc[b*DD + d] = c;
        QO[b*KCAT + 256 + d] = h;
        QO[b*KCAT + d]       = h;
    }
}

// ---------------- single-pass online-softmax attention (+ fused pred) --------
__global__ __launch_bounds__(256) void k_attn(int sel, int last,
                                              const float* __restrict__ Wp,
                                              const float* __restrict__ bp,
                                              float* __restrict__ out) {
    __shared__ __align__(16) float qsm[DD];
    __shared__ __align__(16) float wacc[8][DD];
    __shared__ float wm[8], ws[8], psum[4];
    int b = blockIdx.x, t = threadIdx.x;
    float* __restrict__ Q = g_qh[sel];
    if (t < DD) qsm[t] = Q[b*KCAT + 256 + t];
    __syncthreads();
    int lane = t & 31, w = t >> 5;
    int base = lane*4;
    int ns = g_gptr[b], ne = g_gptr[b+1];
    float4 qv = *(const float4*)(qsm + base);
    float m = -INFINITY, s = 0.f;
    float ax = 0.f, ay = 0.f, az = 0.f, aw2 = 0.f;
    for (int n = ns + w*2; n < ne; n += 16) {
        float h0x,h0y,h0z,h0w;
        h4_to_f4(*(const uint2*)(g_h16A + n*DD + base), h0x,h0y,h0z,h0w);
        float e0 = h0x*qv.x + h0y*qv.y + h0z*qv.z + h0w*qv.w;
        #pragma unroll
        for (int off = 16; off > 0; off >>= 1) e0 += __shfl_xor_sync(0xffffffffu, e0, off);
        bool has1 = (n + 1 < ne);
        float h1x=0.f,h1y=0.f,h1z=0.f,h1w=0.f;
        float e1 = -INFINITY;
        if (has1) {
            h4_to_f4(*(const uint2*)(g_h16A + (n+1)*DD + base), h1x,h1y,h1z,h1w);
            e1 = h1x*qv.x + h1y*qv.y + h1z*qv.z + h1w*qv.w;
            #pragma unroll
            for (int off = 16; off > 0; off >>= 1) e1 += __shfl_xor_sync(0xffffffffu, e1, off);
        }
        float m2 = fmaxf(m, fmaxf(e0, e1));
        float c  = expf(m - m2);
        float p0 = expf(e0 - m2);
        float p1 = has1 ? expf(e1 - m2) : 0.f;
        s  = s*c + p0 + p1;
        ax = ax*c + p0*h0x + p1*h1x;
        ay = ay*c + p0*h0y + p1*h1y;
        az = az*c + p0*h0z + p1*h1z;
        aw2= aw2*c+ p0*h0w + p1*h1w;
        m = m2;
    }
    if (lane == 0) { wm[w] = m; ws[w] = s; }
    float4 av; av.x=ax; av.y=ay; av.z=az; av.w=aw2;
    *(float4*)(&wacc[w][base]) = av;
    __syncthreads();
    if (t < DD) {
        float r = 0.f;
        if (ne > ns) {
            float M = wm[0];
            #pragma unroll
            for (int i = 1; i < 8; i++) M = fmaxf(M, wm[i]);
            float denom = 1e-16f, num = 0.f;
            #pragma unroll
            for (int i = 0; i < 8; i++) {
                float sc = expf(wm[i] - M);
                denom += sc * ws[i];
                num   += sc * wacc[i][t];
            }
            r = num / denom;
        }
        Q[b*KCAT + DD + t] = r;
        if (last) {
            float part = qsm[t]*Wp[t] + r*Wp[DD + t];
            #pragma unroll
            for (int off = 16; off > 0; off >>= 1) part += __shfl_xor_sync(0xffffffffu, part, off);
            if (lane == 0) psum[t >> 5] = part;
        }
    }
    __syncthreads();
    if (last && t == 0) out[b] = psum[0] + psum[1] + psum[2] + psum[3] + bp[0];
}

// ---------------- launch ----------------
extern "C" void kernel_launch(void* const* d_in, const int* in_sizes, int n_in,
                              void* d_out, int out_size) {
    const float *x=0, *W_in=0, *b_in=0, *W_ih=0, *W_hh=0, *b_ih=0, *b_hh=0, *W_pred=0, *b_pred=0;
    const int *ei=0, *batch=0;
    for (int i = 0; i < n_in; i++) {
        int s = in_sizes[i];
        const void* p = d_in[i];
        switch (s) {
            case 4800000: x      = (const float*)p; break;
            case 1600000: ei     = (const int*)p;   break;
            case 50000:   batch  = (const int*)p;   break;
            case 12288:   W_in   = (const float*)p; break;
            case 128:     b_in   = (const float*)p; break;
            case 131072:  W_ih   = (const float*)p; break;
            case 65536:   W_hh   = (const float*)p; break;
            case 512:     if (!b_ih) b_ih = (const float*)p; else b_hh = (const float*)p; break;
            case 256:     W_pred = (const float*)p; break;
            case 1:       b_pred = (const float*)p; break;
            default: break;
        }
    }
    float* out = (float*)d_out;
    (void)out_size;

    k_init<<<1536, 256>>>(W_in, W_ih, W_hh, b_ih, b_hh);
    k_ingemm_hist<<<NB_GEMM + NB_HIST, 128>>>(x, b_in, ei);
    k_scan1<<<98, 512>>>();
    k_scan2<<<1, 128>>>();
    k_scan3_gptr<<<98, 512>>>(batch);
    k_fill<<<(EE + 255)/256, 256>>>(ei);

    k_mpnn<<<(NN*32 + 127)/128, 128>>>(0);        // A -> B
    k_mpnn<<<(NN*32 + 127)/128, 128>>>(1);        // B -> A
    k_mpnn<<<(NN*32 + 127)/128, 128>>>(0);        // A -> B
    k_mpnn<<<(NN*32 + 127)/128, 128>>>(1);        // B -> A  (final h in g_h16A)

    for (int s = 0; s < 3; s++) {
        int sin = s & 1, sout = (s + 1) & 1;
        k_gates_lstm<<<128, 128>>>(sin, sout);
        k_attn<<<BB, 256>>>(sout, (s == 2) ? 1 : 0, W_pred, b_pred, out);
    }
}